// round 1
// baseline (speedup 1.0000x reference)
#include <cuda_runtime.h>
#include <cuda_bf16.h>
#include <cstdint>

#define B_ANCH 2048
#define P_POS  4
#define D_DIM  256
#define NNEG   32768
#define ALPHA  0.1f
#define EPSN   1e-12f
// 1/TEMPERATURE = 20  (also the upper bound on neg_sim since cosine <= 1)
#define INV_T  20.0f

#define MT      128            // anchor rows per block
#define NCHUNK  2048           // negatives per block (blockIdx.y)
#define NB      64             // negatives per smem sub-tile
#define NCHUNKS (NNEG / NCHUNK)   // 16
#define NSUB    (NCHUNK / NB)     // 32
#define ASTR    (D_DIM + 8)       // padded smem row stride (bf16 elems) -> conflict-free

// ---- scratch (no allocations allowed) ----
__device__ __nv_bfloat16 g_a_bf[B_ANCH * D_DIM];            // 1 MB
__device__ __nv_bfloat16 g_n_bf[NNEG * D_DIM];              // 16 MB
__device__ float g_pos[B_ANCH * P_POS];                     // 32 KB
__device__ float g_part[B_ANCH * NCHUNKS];                  // 128 KB

// ============================================================
// Kernel 1: L2-normalize anchors + negatives -> bf16
// one warp per row of 256 floats
// ============================================================
__global__ void normalize_kernel(const float* __restrict__ anch,
                                 const float* __restrict__ neg) {
    int warp = threadIdx.x >> 5, lane = threadIdx.x & 31;
    int row = blockIdx.x * 8 + warp;
    const float* src;
    __nv_bfloat16* dst;
    if (row < B_ANCH) {
        src = anch + (size_t)row * D_DIM;
        dst = g_a_bf + (size_t)row * D_DIM;
    } else {
        int r = row - B_ANCH;
        if (r >= NNEG) return;
        src = neg + (size_t)r * D_DIM;
        dst = g_n_bf + (size_t)r * D_DIM;
    }
    const float4* s4 = (const float4*)src;
    float4 v0 = s4[lane];
    float4 v1 = s4[lane + 32];
    float ss = v0.x*v0.x + v0.y*v0.y + v0.z*v0.z + v0.w*v0.w
             + v1.x*v1.x + v1.y*v1.y + v1.z*v1.z + v1.w*v1.w;
    #pragma unroll
    for (int o = 16; o; o >>= 1) ss += __shfl_xor_sync(0xFFFFFFFFu, ss, o);
    float inv = 1.0f / fmaxf(sqrtf(ss), EPSN);
    __nv_bfloat162* d2 = (__nv_bfloat162*)dst;
    d2[2*lane + 0]  = __floats2bfloat162_rn(v0.x*inv, v0.y*inv);
    d2[2*lane + 1]  = __floats2bfloat162_rn(v0.z*inv, v0.w*inv);
    d2[2*lane + 64] = __floats2bfloat162_rn(v1.x*inv, v1.y*inv);
    d2[2*lane + 65] = __floats2bfloat162_rn(v1.z*inv, v1.w*inv);
}

// ============================================================
// Kernel 2: pos_sim[b][j] = (a.p)/(|a||p|) / T   in fp32
// one warp per (anchor, positive) pair
// ============================================================
__global__ void pos_kernel(const float* __restrict__ anch,
                           const float* __restrict__ pos) {
    int warp = threadIdx.x >> 5, lane = threadIdx.x & 31;
    int id = blockIdx.x * 8 + warp;        // 0 .. B*P-1
    if (id >= B_ANCH * P_POS) return;
    int b = id >> 2;
    const float4* a4 = (const float4*)(anch + (size_t)b * D_DIM);
    const float4* p4 = (const float4*)(pos  + (size_t)id * D_DIM);
    float4 a0 = a4[lane], a1 = a4[lane + 32];
    float4 p0 = p4[lane], p1 = p4[lane + 32];
    float dot = a0.x*p0.x + a0.y*p0.y + a0.z*p0.z + a0.w*p0.w
              + a1.x*p1.x + a1.y*p1.y + a1.z*p1.z + a1.w*p1.w;
    float asq = a0.x*a0.x + a0.y*a0.y + a0.z*a0.z + a0.w*a0.w
              + a1.x*a1.x + a1.y*a1.y + a1.z*a1.z + a1.w*a1.w;
    float psq = p0.x*p0.x + p0.y*p0.y + p0.z*p0.z + p0.w*p0.w
              + p1.x*p1.x + p1.y*p1.y + p1.z*p1.z + p1.w*p1.w;
    #pragma unroll
    for (int o = 16; o; o >>= 1) {
        dot += __shfl_xor_sync(0xFFFFFFFFu, dot, o);
        asq += __shfl_xor_sync(0xFFFFFFFFu, asq, o);
        psq += __shfl_xor_sync(0xFFFFFFFFu, psq, o);
    }
    if (lane == 0) {
        float denom = fmaxf(sqrtf(asq), EPSN) * fmaxf(sqrtf(psq), EPSN);
        g_pos[id] = dot / denom * INV_T;
    }
}

// ============================================================
// Kernel 3: fused GEMM (a @ n^T) + sum(exp(x - 20)) per row-chunk
// block: 256 threads (8 warps), tile MT=128 anchors x NCHUNK=2048 negs
// warp w owns rows [16w, 16w+16); mma.sync m16n8k16 bf16
// ============================================================
extern __shared__ __nv_bfloat16 smem_g[];

__global__ void __launch_bounds__(256, 2) gemm_lse_kernel() {
    __nv_bfloat16* sA = smem_g;                 // MT x ASTR
    __nv_bfloat16* sB = smem_g + MT * ASTR;     // NB x ASTR

    int tid = threadIdx.x;
    int w = tid >> 5, lane = tid & 31, g = lane >> 2, q = lane & 3;
    int m0 = blockIdx.x * MT;
    int n0 = blockIdx.y * NCHUNK;

    // Load the A tile once (reused for the whole N chunk).
    const uint4* gA = (const uint4*)(g_a_bf + (size_t)m0 * D_DIM);
    #pragma unroll
    for (int i = tid; i < MT * 32; i += 256) {
        int r = i >> 5, c = i & 31;
        *((uint4*)(sA + r * ASTR) + c) = gA[i];
    }
    __syncthreads();

    float rs0 = 0.0f, rs1 = 0.0f;   // running sum(exp) for rows g and g+8

    for (int nb = 0; nb < NSUB; nb++) {
        const uint4* gB = (const uint4*)(g_n_bf + (size_t)(n0 + nb * NB) * D_DIM);
        #pragma unroll
        for (int i = tid; i < NB * 32; i += 256) {
            int r = i >> 5, c = i & 31;
            *((uint4*)(sB + r * ASTR) + c) = gB[i];
        }
        __syncthreads();

        float acc[8][4];
        #pragma unroll
        for (int j = 0; j < 8; j++) {
            acc[j][0] = 0.f; acc[j][1] = 0.f; acc[j][2] = 0.f; acc[j][3] = 0.f;
        }

        const __nv_bfloat16* sAw = sA + (size_t)(w * 16) * ASTR;
        #pragma unroll
        for (int ks = 0; ks < 16; ks++) {
            int k0 = ks * 16;
            uint32_t ra0 = *(const uint32_t*)(sAw + (size_t)g       * ASTR + k0 + 2*q);
            uint32_t ra1 = *(const uint32_t*)(sAw + (size_t)(g + 8) * ASTR + k0 + 2*q);
            uint32_t ra2 = *(const uint32_t*)(sAw + (size_t)g       * ASTR + k0 + 2*q + 8);
            uint32_t ra3 = *(const uint32_t*)(sAw + (size_t)(g + 8) * ASTR + k0 + 2*q + 8);
            #pragma unroll
            for (int j = 0; j < 8; j++) {
                const __nv_bfloat16* sBr = sB + (size_t)(j * 8 + g) * ASTR + k0 + 2*q;
                uint32_t rb0 = *(const uint32_t*)(sBr);
                uint32_t rb1 = *(const uint32_t*)(sBr + 8);
                asm volatile(
                    "mma.sync.aligned.m16n8k16.row.col.f32.bf16.bf16.f32 "
                    "{%0,%1,%2,%3}, {%4,%5,%6,%7}, {%8,%9}, {%0,%1,%2,%3};\n"
                    : "+f"(acc[j][0]), "+f"(acc[j][1]), "+f"(acc[j][2]), "+f"(acc[j][3])
                    : "r"(ra0), "r"(ra1), "r"(ra2), "r"(ra3), "r"(rb0), "r"(rb1));
            }
        }

        // epilogue: x = cos * 20; accumulate exp(x - 20) = __expf(20*(cos-1))
        #pragma unroll
        for (int j = 0; j < 8; j++) {
            rs0 += __expf(fmaf(acc[j][0], INV_T, -INV_T))
                 + __expf(fmaf(acc[j][1], INV_T, -INV_T));
            rs1 += __expf(fmaf(acc[j][2], INV_T, -INV_T))
                 + __expf(fmaf(acc[j][3], INV_T, -INV_T));
        }
        __syncthreads();
    }

    // reduce across the 4 threads of each quad (same row-group g)
    rs0 += __shfl_xor_sync(0xFFFFFFFFu, rs0, 1);
    rs0 += __shfl_xor_sync(0xFFFFFFFFu, rs0, 2);
    rs1 += __shfl_xor_sync(0xFFFFFFFFu, rs1, 1);
    rs1 += __shfl_xor_sync(0xFFFFFFFFu, rs1, 2);
    if (q == 0) {
        int row = m0 + w * 16 + g;
        g_part[(size_t)row * NCHUNKS + blockIdx.y]       = rs0;
        g_part[(size_t)(row + 8) * NCHUNKS + blockIdx.y] = rs1;
    }
}

// ============================================================
// Kernel 4: finalize (single block, deterministic reduction)
// ============================================================
__global__ void finalize_kernel(const int* __restrict__ counts,
                                float* __restrict__ out) {
    __shared__ float red[256];
    int tid = threadIdx.x;
    float local = 0.0f;
    for (int b = tid; b < B_ANCH; b += 256) {
        float s = 0.0f;
        #pragma unroll
        for (int c = 0; c < NCHUNKS; c++) s += g_part[(size_t)b * NCHUNKS + c];
        float lse = 20.0f + logf(s);
        int cnt = counts[b];
        float ps[4];
        #pragma unroll
        for (int j = 0; j < 4; j++) ps[j] = g_pos[b * 4 + j];

        // per-pair CE terms: logaddexp(pos, lse) - pos
        #pragma unroll
        for (int j = 0; j < 4; j++) {
            if (j < cnt) {
                float m = fmaxf(ps[j], lse);
                float l = m + log1pf(expf(fminf(ps[j], lse) - m));
                local += l - ps[j];
            }
        }
        // weighted-positive term: softmax over the full P axis (as reference)
        float mx = fmaxf(fmaxf(ps[0], ps[1]), fmaxf(ps[2], ps[3]));
        float e0 = expf(ps[0] - mx), e1 = expf(ps[1] - mx);
        float e2 = expf(ps[2] - mx), e3 = expf(ps[3] - mx);
        float den = e0 + e1 + e2 + e3;
        float wps = (e0*ps[0] + e1*ps[1] + e2*ps[2] + e3*ps[3]) / den;
        if (cnt > 1) {
            float m = fmaxf(wps, lse);
            float wl = m + log1pf(expf(fminf(wps, lse) - m)) - wps;
            local += ALPHA * wl;
        }
    }
    red[tid] = local;
    __syncthreads();
    #pragma unroll
    for (int o = 128; o; o >>= 1) {
        if (tid < o) red[tid] += red[tid + o];
        __syncthreads();
    }
    if (tid == 0) out[0] = red[0] / (float)B_ANCH;
}

// ============================================================
extern "C" void kernel_launch(void* const* d_in, const int* in_sizes, int n_in,
                              void* d_out, int out_size) {
    const float* anch   = (const float*)d_in[0];
    const float* pos    = (const float*)d_in[1];
    const float* neg    = (const float*)d_in[2];
    const int*   counts = (const int*)d_in[3];
    float* out = (float*)d_out;

    size_t smem_bytes = (size_t)(MT * ASTR + NB * ASTR) * sizeof(__nv_bfloat16);
    cudaFuncSetAttribute(gemm_lse_kernel,
                         cudaFuncAttributeMaxDynamicSharedMemorySize,
                         (int)smem_bytes);

    normalize_kernel<<<(B_ANCH + NNEG) / 8, 256>>>(anch, neg);
    pos_kernel<<<(B_ANCH * P_POS) / 8, 256>>>(anch, pos);
    dim3 grid(B_ANCH / MT, NCHUNKS);
    gemm_lse_kernel<<<grid, 256, smem_bytes>>>();
    finalize_kernel<<<1, 256>>>(counts, out);
}

// round 4
// speedup vs baseline: 1.3006x; 1.3006x over previous
#include <cuda_runtime.h>
#include <cuda_bf16.h>
#include <cstdint>

#define B_ANCH 2048
#define P_POS  4
#define D_DIM  256            // K
#define NNEG   32768
#define ALPHA  0.1f
#define EPSN   1e-12f
#define INV_T  20.0f          // 1/temperature; bound on neg_sim (cos<=1)

#define MT     128            // anchors per CTA
#define NB     64             // negatives per subtile
#define NSUBT  (NNEG / NB)    // 512 subtiles per M-block
#define MBLKS  (B_ANCH / MT)  // 16
#define NGRP   18             // N-groups -> grid 16*18 = 288 CTAs
#define STR    272            // smem row stride bytes (256 data + 16 pad)

#define A_BYTES (MT * STR)          // 34816
#define B_BYTES (NB * STR)          // 17408
#define SMEM_TOTAL (A_BYTES + 3 * B_BYTES)   // 87040

// ---- scratch ----
__device__ uint8_t g_a8[B_ANCH * D_DIM];      // e4m3
__device__ uint8_t g_n8[NNEG * D_DIM];        // e4m3
__device__ float g_pos[B_ANCH * P_POS];
__device__ float g_part[B_ANCH * NGRP];
__device__ float g_bsum[8];

// ================= helpers =================
__device__ __forceinline__ uint32_t smem_u32(const void* p) {
    uint32_t a;
    asm("{ .reg .u64 t; cvta.to.shared.u64 t, %1; cvt.u32.u64 %0, t; }" : "=r"(a) : "l"(p));
    return a;
}
__device__ __forceinline__ void cp_async16(uint32_t dst, const void* src) {
    asm volatile("cp.async.cg.shared.global [%0], [%1], 16;" :: "r"(dst), "l"(src) : "memory");
}
#define CP_COMMIT() asm volatile("cp.async.commit_group;" ::: "memory")
#define CP_WAIT(n)  asm volatile("cp.async.wait_group %0;" :: "n"(n) : "memory")

__device__ __forceinline__ uint32_t pack_e4m3_4(float x, float y, float z, float w) {
    uint16_t lo, hi;
    asm("cvt.rn.satfinite.e4m3x2.f32 %0, %1, %2;" : "=h"(lo) : "f"(y), "f"(x));
    asm("cvt.rn.satfinite.e4m3x2.f32 %0, %1, %2;" : "=h"(hi) : "f"(w), "f"(z));
    return (uint32_t)lo | ((uint32_t)hi << 16);
}

__device__ __forceinline__ void mma_fp8(float* c, const uint32_t* a,
                                        uint32_t b0, uint32_t b1) {
    asm volatile(
        "mma.sync.aligned.m16n8k32.row.col.f32.e4m3.e4m3.f32 "
        "{%0,%1,%2,%3}, {%4,%5,%6,%7}, {%8,%9}, {%0,%1,%2,%3};\n"
        : "+f"(c[0]), "+f"(c[1]), "+f"(c[2]), "+f"(c[3])
        : "r"(a[0]), "r"(a[1]), "r"(a[2]), "r"(a[3]), "r"(b0), "r"(b1));
}

// ============================================================
// Kernel 1: L2-normalize anchors + negatives -> e4m3
// one warp per row of 256 floats
// ============================================================
__global__ void normalize_kernel(const float* __restrict__ anch,
                                 const float* __restrict__ neg) {
    int warp = threadIdx.x >> 5, lane = threadIdx.x & 31;
    int row = blockIdx.x * 8 + warp;
    const float* src;
    uint8_t* dst;
    if (row < B_ANCH) {
        src = anch + (size_t)row * D_DIM;  dst = g_a8 + (size_t)row * D_DIM;
    } else {
        int r = row - B_ANCH;
        if (r >= NNEG) return;
        src = neg + (size_t)r * D_DIM;     dst = g_n8 + (size_t)r * D_DIM;
    }
    const float4* s4 = (const float4*)src;
    float4 v0 = s4[lane], v1 = s4[lane + 32];
    float ss = v0.x*v0.x + v0.y*v0.y + v0.z*v0.z + v0.w*v0.w
             + v1.x*v1.x + v1.y*v1.y + v1.z*v1.z + v1.w*v1.w;
    #pragma unroll
    for (int o = 16; o; o >>= 1) ss += __shfl_xor_sync(0xFFFFFFFFu, ss, o);
    float inv = 1.0f / fmaxf(sqrtf(ss), EPSN);
    uint32_t* d32 = (uint32_t*)dst;
    d32[lane]      = pack_e4m3_4(v0.x*inv, v0.y*inv, v0.z*inv, v0.w*inv);
    d32[lane + 32] = pack_e4m3_4(v1.x*inv, v1.y*inv, v1.z*inv, v1.w*inv);
}

// ============================================================
// Kernel 2: pos_sim in fp32 (warp per pair) — exact
// ============================================================
__global__ void pos_kernel(const float* __restrict__ anch,
                           const float* __restrict__ pos) {
    int warp = threadIdx.x >> 5, lane = threadIdx.x & 31;
    int id = blockIdx.x * 8 + warp;
    if (id >= B_ANCH * P_POS) return;
    int b = id >> 2;
    const float4* a4 = (const float4*)(anch + (size_t)b * D_DIM);
    const float4* p4 = (const float4*)(pos  + (size_t)id * D_DIM);
    float4 a0 = a4[lane], a1 = a4[lane + 32];
    float4 p0 = p4[lane], p1 = p4[lane + 32];
    float dot = a0.x*p0.x + a0.y*p0.y + a0.z*p0.z + a0.w*p0.w
              + a1.x*p1.x + a1.y*p1.y + a1.z*p1.z + a1.w*p1.w;
    float asq = a0.x*a0.x + a0.y*a0.y + a0.z*a0.z + a0.w*a0.w
              + a1.x*a1.x + a1.y*a1.y + a1.z*a1.z + a1.w*a1.w;
    float psq = p0.x*p0.x + p0.y*p0.y + p0.z*p0.z + p0.w*p0.w
              + p1.x*p1.x + p1.y*p1.y + p1.z*p1.z + p1.w*p1.w;
    #pragma unroll
    for (int o = 16; o; o >>= 1) {
        dot += __shfl_xor_sync(0xFFFFFFFFu, dot, o);
        asq += __shfl_xor_sync(0xFFFFFFFFu, asq, o);
        psq += __shfl_xor_sync(0xFFFFFFFFu, psq, o);
    }
    if (lane == 0) {
        float denom = fmaxf(sqrtf(asq), EPSN) * fmaxf(sqrtf(psq), EPSN);
        g_pos[id] = dot / denom * INV_T;
    }
}

// ============================================================
// Kernel 3: fp8 mma.sync GEMM + fused sum(exp(20*(cos-1)))
// 256 threads / 8 warps; warp w owns rows 16w..16w+15.
// A fragments register-resident; B triple-buffered via cp.async.
// grid = 16 M-blocks x 18 N-groups = 288 CTAs (one wave @ occ 2)
// ============================================================
extern __shared__ uint8_t smem_raw[];

__global__ void __launch_bounds__(256, 2) gemm_lse_kernel() {
    uint8_t* sA = smem_raw;
    uint32_t sA_u = smem_u32(smem_raw);
    int tid = threadIdx.x;
    int w = tid >> 5, lane = tid & 31, g = lane >> 2, q = lane & 3;
    int m  = blockIdx.x & 15;
    int gp = blockIdx.x >> 4;
    int m0 = m * MT;
    int tstart = gp * 28 + min(gp, 8);      // 512 = 8*29 + 10*28
    int tcnt   = 28 + (gp < 8 ? 1 : 0);

    // ---- issue A tile load (32KB, 2048 x 16B chunks) ----
    {
        const uint8_t* gA = g_a8 + (size_t)m0 * D_DIM;
        #pragma unroll
        for (int i = 0; i < 8; i++) {
            int c = tid + i * 256;
            int r = c >> 4, c16 = c & 15;
            cp_async16(sA_u + r * STR + c16 * 16, gA + (size_t)r * 256 + c16 * 16);
        }
    }
    CP_COMMIT();

    // ---- preload B tiles 0,1 ----
    #pragma unroll
    for (int pb = 0; pb < 2; pb++) {
        const uint8_t* gB = g_n8 + (size_t)(tstart + pb) * NB * D_DIM;
        uint32_t sB_u = sA_u + A_BYTES + pb * B_BYTES;
        #pragma unroll
        for (int i = 0; i < 4; i++) {
            int c = tid + i * 256;
            int r = c >> 4, c16 = c & 15;
            cp_async16(sB_u + r * STR + c16 * 16, gB + (size_t)r * 256 + c16 * 16);
        }
        CP_COMMIT();
    }

    // ---- A fragments -> registers (32 regs), A smem dead afterwards ----
    CP_WAIT(2);     // A tile complete
    __syncthreads();
    uint32_t areg[32];
    {
        const uint8_t* r0 = sA + (size_t)(w * 16 + g) * STR;
        const uint8_t* r1 = r0 + 8 * STR;
        #pragma unroll
        for (int ks = 0; ks < 8; ks++) {
            int k0 = ks * 32;
            areg[4*ks+0] = *(const uint32_t*)(r0 + k0 + 4*q);
            areg[4*ks+1] = *(const uint32_t*)(r1 + k0 + 4*q);
            areg[4*ks+2] = *(const uint32_t*)(r0 + k0 + 16 + 4*q);
            areg[4*ks+3] = *(const uint32_t*)(r1 + k0 + 16 + 4*q);
        }
    }

    float rs0 = 0.0f, rs1 = 0.0f;

    for (int t = 0; t < tcnt; t++) {
        if (t < tcnt - 1) CP_WAIT(1); else CP_WAIT(0);
        __syncthreads();

        // prefetch tile t+2 into buffer (t+2)%3 (consumed at iter t-1)
        if (t + 2 < tcnt) {
            const uint8_t* gB = g_n8 + (size_t)(tstart + t + 2) * NB * D_DIM;
            uint32_t sB_u = sA_u + A_BYTES + ((t + 2) % 3) * B_BYTES;
            #pragma unroll
            for (int i = 0; i < 4; i++) {
                int c = tid + i * 256;
                int r = c >> 4, c16 = c & 15;
                cp_async16(sB_u + r * STR + c16 * 16, gB + (size_t)r * 256 + c16 * 16);
            }
            CP_COMMIT();
        }

        const uint8_t* sB = sA + A_BYTES + (t % 3) * B_BYTES;
        float acc[8][4];
        #pragma unroll
        for (int j = 0; j < 8; j++) {
            acc[j][0] = 0.f; acc[j][1] = 0.f; acc[j][2] = 0.f; acc[j][3] = 0.f;
        }

        #pragma unroll
        for (int ks = 0; ks < 8; ks++) {
            int k0 = ks * 32;
            #pragma unroll
            for (int j = 0; j < 8; j++) {
                const uint8_t* br = sB + (size_t)(j * 8 + g) * STR + k0 + 4*q;
                uint32_t b0 = *(const uint32_t*)(br);
                uint32_t b1 = *(const uint32_t*)(br + 16);
                mma_fp8(acc[j], areg + 4*ks, b0, b1);
            }
        }

        // epilogue: accumulate exp(20*(cos-1)) (== exp(logit - 20), stable)
        #pragma unroll
        for (int j = 0; j < 8; j++) {
            rs0 += __expf(fmaf(acc[j][0], INV_T, -INV_T))
                 + __expf(fmaf(acc[j][1], INV_T, -INV_T));
            rs1 += __expf(fmaf(acc[j][2], INV_T, -INV_T))
                 + __expf(fmaf(acc[j][3], INV_T, -INV_T));
        }
    }

    // reduce across the quad (cols), write per-row partials
    rs0 += __shfl_xor_sync(0xFFFFFFFFu, rs0, 1);
    rs0 += __shfl_xor_sync(0xFFFFFFFFu, rs0, 2);
    rs1 += __shfl_xor_sync(0xFFFFFFFFu, rs1, 1);
    rs1 += __shfl_xor_sync(0xFFFFFFFFu, rs1, 2);
    if (q == 0) {
        int row = m0 + w * 16 + g;
        g_part[(size_t)row * NGRP + gp]       = rs0;
        g_part[(size_t)(row + 8) * NGRP + gp] = rs1;
    }
}

// ============================================================
// Kernel 4a: per-anchor loss + block partial sums (grid 8)
// ============================================================
__global__ void finalize_a_kernel(const int* __restrict__ counts) {
    __shared__ float red[256];
    int tid = threadIdx.x;
    int b = blockIdx.x * 256 + tid;

    float s = 0.0f;
    #pragma unroll
    for (int c = 0; c < NGRP; c++) s += g_part[(size_t)b * NGRP + c];
    float lse = 20.0f + logf(s);
    int cnt = counts[b];
    float ps[4];
    #pragma unroll
    for (int j = 0; j < 4; j++) ps[j] = g_pos[b * 4 + j];

    float local = 0.0f;
    #pragma unroll
    for (int j = 0; j < 4; j++) {
        if (j < cnt) {
            float mx = fmaxf(ps[j], lse);
            local += mx + log1pf(expf(fminf(ps[j], lse) - mx)) - ps[j];
        }
    }
    float mx = fmaxf(fmaxf(ps[0], ps[1]), fmaxf(ps[2], ps[3]));
    float e0 = expf(ps[0] - mx), e1 = expf(ps[1] - mx);
    float e2 = expf(ps[2] - mx), e3 = expf(ps[3] - mx);
    float wps = (e0*ps[0] + e1*ps[1] + e2*ps[2] + e3*ps[3]) / (e0 + e1 + e2 + e3);
    if (cnt > 1) {
        float m2 = fmaxf(wps, lse);
        local += ALPHA * (m2 + log1pf(expf(fminf(wps, lse) - m2)) - wps);
    }

    red[tid] = local;
    __syncthreads();
    #pragma unroll
    for (int o = 128; o; o >>= 1) {
        if (tid < o) red[tid] += red[tid + o];
        __syncthreads();
    }
    if (tid == 0) g_bsum[blockIdx.x] = red[0];
}

__global__ void finalize_b_kernel(float* __restrict__ out) {
    if (threadIdx.x == 0) {
        float t = 0.0f;
        #pragma unroll
        for (int i = 0; i < 8; i++) t += g_bsum[i];
        out[0] = t / (float)B_ANCH;
    }
}

// ============================================================
extern "C" void kernel_launch(void* const* d_in, const int* in_sizes, int n_in,
                              void* d_out, int out_size) {
    const float* anch   = (const float*)d_in[0];
    const float* pos    = (const float*)d_in[1];
    const float* neg    = (const float*)d_in[2];
    const int*   counts = (const int*)d_in[3];
    float* out = (float*)d_out;

    cudaFuncSetAttribute(gemm_lse_kernel,
                         cudaFuncAttributeMaxDynamicSharedMemorySize, SMEM_TOTAL);

    normalize_kernel<<<(B_ANCH + NNEG) / 8, 256>>>(anch, neg);
    pos_kernel<<<(B_ANCH * P_POS) / 8, 256>>>(anch, pos);
    gemm_lse_kernel<<<MBLKS * NGRP, 256, SMEM_TOTAL>>>();
    finalize_a_kernel<<<8, 256>>>(counts);
    finalize_b_kernel<<<1, 32>>>(out);
}

// round 5
// speedup vs baseline: 1.3726x; 1.0553x over previous
#include <cuda_runtime.h>
#include <cuda_fp16.h>
#include <cstdint>

#define B_ANCH 2048
#define P_POS  4
#define D_DIM  256            // K
#define NNEG   32768
#define ALPHA  0.1f
#define EPSN   1e-12f
#define INV_T  20.0f          // 1/temperature; bound on neg_sim (cos<=1)

#define MT     128            // anchors per CTA
#define NB     64             // negatives per subtile
#define MBLKS  (B_ANCH / MT)  // 16
#define NGRP   18             // N-groups -> grid 16*18 = 288 CTAs
#define STR    272            // smem row stride bytes (256 data + 16 pad)

#define A_BYTES (MT * STR)          // 34816
#define B_BYTES (NB * STR)          // 17408
#define SMEM_TOTAL (A_BYTES + 3 * B_BYTES)   // 87040

// ---- scratch ----
__device__ uint8_t g_a8[B_ANCH * D_DIM];      // e4m3
__device__ uint8_t g_n8[NNEG * D_DIM];        // e4m3
__device__ float g_pos[B_ANCH * P_POS];
__device__ float g_part[NGRP * B_ANCH];       // transposed: [gp][anchor]
__device__ float g_bsum[16];

// ================= helpers =================
__device__ __forceinline__ uint32_t smem_u32(const void* p) {
    uint32_t a;
    asm("{ .reg .u64 t; cvta.to.shared.u64 t, %1; cvt.u32.u64 %0, t; }" : "=r"(a) : "l"(p));
    return a;
}
__device__ __forceinline__ void cp_async16(uint32_t dst, const void* src) {
    asm volatile("cp.async.cg.shared.global [%0], [%1], 16;" :: "r"(dst), "l"(src) : "memory");
}
#define CP_COMMIT() asm volatile("cp.async.commit_group;" ::: "memory")
#define CP_WAIT(n)  asm volatile("cp.async.wait_group %0;" :: "n"(n) : "memory")

__device__ __forceinline__ uint32_t pack_e4m3_4(float x, float y, float z, float w) {
    uint16_t lo, hi;
    asm("cvt.rn.satfinite.e4m3x2.f32 %0, %1, %2;" : "=h"(lo) : "f"(y), "f"(x));
    asm("cvt.rn.satfinite.e4m3x2.f32 %0, %1, %2;" : "=h"(hi) : "f"(w), "f"(z));
    return (uint32_t)lo | ((uint32_t)hi << 16);
}

// fp8 mma with f16 accumulators (2x rate vs f32 acc on legacy HMMA path)
// d0 halves = rows g, cols (2q, 2q+1); d1 halves = rows g+8.
__device__ __forceinline__ void mma_fp8_h(uint32_t* c, const uint32_t* a,
                                          uint32_t b0, uint32_t b1) {
    asm volatile(
        "mma.sync.aligned.m16n8k32.row.col.f16.e4m3.e4m3.f16 "
        "{%0,%1}, {%2,%3,%4,%5}, {%6,%7}, {%0,%1};\n"
        : "+r"(c[0]), "+r"(c[1])
        : "r"(a[0]), "r"(a[1]), "r"(a[2]), "r"(a[3]), "r"(b0), "r"(b1));
}

// ============================================================
// Kernel 1: L2-normalize anchors + negatives -> e4m3
// ============================================================
__global__ void normalize_kernel(const float* __restrict__ anch,
                                 const float* __restrict__ neg) {
    int warp = threadIdx.x >> 5, lane = threadIdx.x & 31;
    int row = blockIdx.x * 8 + warp;
    const float* src;
    uint8_t* dst;
    if (row < B_ANCH) {
        src = anch + (size_t)row * D_DIM;  dst = g_a8 + (size_t)row * D_DIM;
    } else {
        int r = row - B_ANCH;
        if (r >= NNEG) return;
        src = neg + (size_t)r * D_DIM;     dst = g_n8 + (size_t)r * D_DIM;
    }
    const float4* s4 = (const float4*)src;
    float4 v0 = s4[lane], v1 = s4[lane + 32];
    float ss = v0.x*v0.x + v0.y*v0.y + v0.z*v0.z + v0.w*v0.w
             + v1.x*v1.x + v1.y*v1.y + v1.z*v1.z + v1.w*v1.w;
    #pragma unroll
    for (int o = 16; o; o >>= 1) ss += __shfl_xor_sync(0xFFFFFFFFu, ss, o);
    float inv = 1.0f / fmaxf(sqrtf(ss), EPSN);
    uint32_t* d32 = (uint32_t*)dst;
    d32[lane]      = pack_e4m3_4(v0.x*inv, v0.y*inv, v0.z*inv, v0.w*inv);
    d32[lane + 32] = pack_e4m3_4(v1.x*inv, v1.y*inv, v1.z*inv, v1.w*inv);
}

// ============================================================
// Kernel 2: pos_sim in fp32 (warp per pair) — exact
// ============================================================
__global__ void pos_kernel(const float* __restrict__ anch,
                           const float* __restrict__ pos) {
    int warp = threadIdx.x >> 5, lane = threadIdx.x & 31;
    int id = blockIdx.x * 8 + warp;
    if (id >= B_ANCH * P_POS) return;
    int b = id >> 2;
    const float4* a4 = (const float4*)(anch + (size_t)b * D_DIM);
    const float4* p4 = (const float4*)(pos  + (size_t)id * D_DIM);
    float4 a0 = a4[lane], a1 = a4[lane + 32];
    float4 p0 = p4[lane], p1 = p4[lane + 32];
    float dot = a0.x*p0.x + a0.y*p0.y + a0.z*p0.z + a0.w*p0.w
              + a1.x*p1.x + a1.y*p1.y + a1.z*p1.z + a1.w*p1.w;
    float asq = a0.x*a0.x + a0.y*a0.y + a0.z*a0.z + a0.w*a0.w
              + a1.x*a1.x + a1.y*a1.y + a1.z*a1.z + a1.w*a1.w;
    float psq = p0.x*p0.x + p0.y*p0.y + p0.z*p0.z + p0.w*p0.w
              + p1.x*p1.x + p1.y*p1.y + p1.z*p1.z + p1.w*p1.w;
    #pragma unroll
    for (int o = 16; o; o >>= 1) {
        dot += __shfl_xor_sync(0xFFFFFFFFu, dot, o);
        asq += __shfl_xor_sync(0xFFFFFFFFu, asq, o);
        psq += __shfl_xor_sync(0xFFFFFFFFu, psq, o);
    }
    if (lane == 0) {
        float denom = fmaxf(sqrtf(asq), EPSN) * fmaxf(sqrtf(psq), EPSN);
        g_pos[id] = dot / denom * INV_T;
    }
}

// ============================================================
// Kernel 3: fp8 mma.sync (f16 acc) GEMM + fused sum(exp(20*(cos-1)))
// 256 threads / 8 warps; warp w owns rows 16w..16w+15.
// A fragments register-resident; B triple-buffered via cp.async.
// ============================================================
extern __shared__ uint8_t smem_raw[];

__global__ void __launch_bounds__(256, 2) gemm_lse_kernel() {
    uint8_t* sA = smem_raw;
    uint32_t sA_u = smem_u32(smem_raw);
    int tid = threadIdx.x;
    int w = tid >> 5, lane = tid & 31, g = lane >> 2, q = lane & 3;
    int m  = blockIdx.x & 15;
    int gp = blockIdx.x >> 4;
    int m0 = m * MT;
    int tstart = gp * 28 + min(gp, 8);      // 512 = 8*29 + 10*28
    int tcnt   = 28 + (gp < 8 ? 1 : 0);

    // ---- issue A tile load (32KB) ----
    {
        const uint8_t* gA = g_a8 + (size_t)m0 * D_DIM;
        #pragma unroll
        for (int i = 0; i < 8; i++) {
            int c = tid + i * 256;
            int r = c >> 4, c16 = c & 15;
            cp_async16(sA_u + r * STR + c16 * 16, gA + (size_t)r * 256 + c16 * 16);
        }
    }
    CP_COMMIT();

    // ---- preload B tiles 0,1 ----
    #pragma unroll
    for (int pb = 0; pb < 2; pb++) {
        const uint8_t* gB = g_n8 + (size_t)(tstart + pb) * NB * D_DIM;
        uint32_t sB_u = sA_u + A_BYTES + pb * B_BYTES;
        #pragma unroll
        for (int i = 0; i < 4; i++) {
            int c = tid + i * 256;
            int r = c >> 4, c16 = c & 15;
            cp_async16(sB_u + r * STR + c16 * 16, gB + (size_t)r * 256 + c16 * 16);
        }
        CP_COMMIT();
    }

    // ---- A fragments -> registers ----
    CP_WAIT(2);
    __syncthreads();
    uint32_t areg[32];
    {
        const uint8_t* r0 = sA + (size_t)(w * 16 + g) * STR;
        const uint8_t* r1 = r0 + 8 * STR;
        #pragma unroll
        for (int ks = 0; ks < 8; ks++) {
            int k0 = ks * 32;
            areg[4*ks+0] = *(const uint32_t*)(r0 + k0 + 4*q);
            areg[4*ks+1] = *(const uint32_t*)(r1 + k0 + 4*q);
            areg[4*ks+2] = *(const uint32_t*)(r0 + k0 + 16 + 4*q);
            areg[4*ks+3] = *(const uint32_t*)(r1 + k0 + 16 + 4*q);
        }
    }

    float rs0 = 0.0f, rs1 = 0.0f;

    for (int t = 0; t < tcnt; t++) {
        if (t < tcnt - 1) CP_WAIT(1); else CP_WAIT(0);
        __syncthreads();

        // prefetch tile t+2 into buffer (t+2)%3
        if (t + 2 < tcnt) {
            const uint8_t* gB = g_n8 + (size_t)(tstart + t + 2) * NB * D_DIM;
            uint32_t sB_u = sA_u + A_BYTES + ((t + 2) % 3) * B_BYTES;
            #pragma unroll
            for (int i = 0; i < 4; i++) {
                int c = tid + i * 256;
                int r = c >> 4, c16 = c & 15;
                cp_async16(sB_u + r * STR + c16 * 16, gB + (size_t)r * 256 + c16 * 16);
            }
            CP_COMMIT();
        }

        const uint8_t* sB = sA + A_BYTES + (t % 3) * B_BYTES;
        uint32_t acc[8][2];
        #pragma unroll
        for (int j = 0; j < 8; j++) { acc[j][0] = 0u; acc[j][1] = 0u; }

        #pragma unroll
        for (int ks = 0; ks < 8; ks++) {
            int k0 = ks * 32;
            #pragma unroll
            for (int j = 0; j < 8; j++) {
                const uint8_t* br = sB + (size_t)(j * 8 + g) * STR + k0 + 4*q;
                uint32_t b0 = *(const uint32_t*)(br);
                uint32_t b1 = *(const uint32_t*)(br + 16);
                mma_fp8_h(acc[j], areg + 4*ks, b0, b1);
            }
        }

        // epilogue: accumulate exp(20*(cos-1)) = exp(logit - 20)  (stable)
        #pragma unroll
        for (int j = 0; j < 8; j++) {
            float2 f0 = __half22float2(*(__half2*)&acc[j][0]);
            float2 f1 = __half22float2(*(__half2*)&acc[j][1]);
            rs0 += __expf(fmaf(f0.x, INV_T, -INV_T))
                 + __expf(fmaf(f0.y, INV_T, -INV_T));
            rs1 += __expf(fmaf(f1.x, INV_T, -INV_T))
                 + __expf(fmaf(f1.y, INV_T, -INV_T));
        }
    }

    // reduce across the quad (cols), write per-row partials (transposed)
    rs0 += __shfl_xor_sync(0xFFFFFFFFu, rs0, 1);
    rs0 += __shfl_xor_sync(0xFFFFFFFFu, rs0, 2);
    rs1 += __shfl_xor_sync(0xFFFFFFFFu, rs1, 1);
    rs1 += __shfl_xor_sync(0xFFFFFFFFu, rs1, 2);
    if (q == 0) {
        int row = m0 + w * 16 + g;
        g_part[(size_t)gp * B_ANCH + row]     = rs0;
        g_part[(size_t)gp * B_ANCH + row + 8] = rs1;
    }
}

// ============================================================
// Kernel 4a: per-anchor loss + block partial sums (grid 16 x 128)
// ============================================================
__global__ void finalize_a_kernel(const int* __restrict__ counts) {
    __shared__ float red[128];
    int tid = threadIdx.x;
    int b = blockIdx.x * 128 + tid;

    float s = 0.0f;
    #pragma unroll
    for (int c = 0; c < NGRP; c++) s += g_part[(size_t)c * B_ANCH + b];
    float lse = 20.0f + logf(s);
    int cnt = counts[b];
    float ps[4];
    #pragma unroll
    for (int j = 0; j < 4; j++) ps[j] = g_pos[b * 4 + j];

    float local = 0.0f;
    #pragma unroll
    for (int j = 0; j < 4; j++) {
        if (j < cnt) {
            float mx = fmaxf(ps[j], lse);
            local += mx + log1pf(expf(fminf(ps[j], lse) - mx)) - ps[j];
        }
    }
    float mx = fmaxf(fmaxf(ps[0], ps[1]), fmaxf(ps[2], ps[3]));
    float e0 = expf(ps[0] - mx), e1 = expf(ps[1] - mx);
    float e2 = expf(ps[2] - mx), e3 = expf(ps[3] - mx);
    float wps = (e0*ps[0] + e1*ps[1] + e2*ps[2] + e3*ps[3]) / (e0 + e1 + e2 + e3);
    if (cnt > 1) {
        float m2 = fmaxf(wps, lse);
        local += ALPHA * (m2 + log1pf(expf(fminf(wps, lse) - m2)) - wps);
    }

    red[tid] = local;
    __syncthreads();
    #pragma unroll
    for (int o = 64; o; o >>= 1) {
        if (tid < o) red[tid] += red[tid + o];
        __syncthreads();
    }
    if (tid == 0) g_bsum[blockIdx.x] = red[0];
}

__global__ void finalize_b_kernel(float* __restrict__ out) {
    if (threadIdx.x == 0) {
        float t = 0.0f;
        #pragma unroll
        for (int i = 0; i < 16; i++) t += g_bsum[i];
        out[0] = t / (float)B_ANCH;
    }
}

// ============================================================
extern "C" void kernel_launch(void* const* d_in, const int* in_sizes, int n_in,
                              void* d_out, int out_size) {
    const float* anch   = (const float*)d_in[0];
    const float* pos    = (const float*)d_in[1];
    const float* neg    = (const float*)d_in[2];
    const int*   counts = (const int*)d_in[3];
    float* out = (float*)d_out;

    cudaFuncSetAttribute(gemm_lse_kernel,
                         cudaFuncAttributeMaxDynamicSharedMemorySize, SMEM_TOTAL);

    normalize_kernel<<<(B_ANCH + NNEG) / 8, 256>>>(anch, neg);
    pos_kernel<<<(B_ANCH * P_POS) / 8, 256>>>(anch, pos);
    gemm_lse_kernel<<<MBLKS * NGRP, 256, SMEM_TOTAL>>>();
    finalize_a_kernel<<<16, 128>>>(counts);
    finalize_b_kernel<<<1, 32>>>(out);
}